// round 1
// baseline (speedup 1.0000x reference)
#include <cuda_runtime.h>
#include <cstdint>
#include <cstddef>

#define DIMC 192
#define NB   8
#define NTOK 4096
#define BR   64
#define BC   64
#define LDQK 196   // 196 % 32 == 4  -> conflict-free Q/K fragment loads
#define LDV  200   // 200 % 32 == 8  -> conflict-free V fragment loads
#define LDP  68    // 68  % 32 == 4  -> conflict-free P fragment loads
#define NTHREADS 128
#define SCALE 0.07216878364870322f   /* 192^-0.5 */

// smem layout (floats)
#define SQ_SZ  (BR*LDQK)
#define SK_SZ  (BC*LDQK)
#define SV_SZ  (BC*LDV)
#define SP_SZ  (4*16*LDP)
#define SMEM_FLOATS (SQ_SZ + SK_SZ + SV_SZ + SP_SZ + 2*64)
#define SMEM_BYTES  (SMEM_FLOATS * 4)

__device__ __forceinline__ float f2tff(float f) {
    uint32_t u;
    asm("cvt.rna.tf32.f32 %0, %1;" : "=r"(u) : "f"(f));
    return __uint_as_float(u);
}

__device__ __forceinline__ void mma8(float* c,
        uint32_t a0, uint32_t a1, uint32_t a2, uint32_t a3,
        uint32_t b0, uint32_t b1) {
    asm volatile("mma.sync.aligned.m16n8k8.row.col.f32.tf32.tf32.f32 "
        "{%0,%1,%2,%3}, {%4,%5,%6,%7}, {%8,%9}, {%0,%1,%2,%3};"
        : "+f"(c[0]), "+f"(c[1]), "+f"(c[2]), "+f"(c[3])
        : "r"(a0), "r"(a1), "r"(a2), "r"(a3), "r"(b0), "r"(b1));
}

__global__ void __launch_bounds__(NTHREADS, 1)
qkv_l2attn_kernel(const float* __restrict__ qkv, float* __restrict__ out)
{
    extern __shared__ float sm[];
    float* sQ  = sm;
    float* sK  = sQ + SQ_SZ;
    float* sV  = sK + SK_SZ;
    float* sP  = sV + SV_SZ;
    float* sQ2 = sP + SP_SZ;
    float* sK2 = sQ2 + 64;

    const int tid  = threadIdx.x;
    const int warp = tid >> 5;
    const int lane = tid & 31;
    const int g    = lane >> 2;   // group (row within 8-row band)
    const int t4   = lane & 3;    // thread-in-group

    const int b  = blockIdx.y;
    const int q0 = blockIdx.x * BR;

    // ---- load Q tile (scaled, tf32-rounded) ----
    const float* qptr = qkv + ((size_t)b * NTOK + q0) * (3 * DIMC);
    for (int idx = tid * 4; idx < BR * DIMC; idx += NTHREADS * 4) {
        int r = idx / DIMC, c = idx % DIMC;
        float4 v = *(const float4*)(qptr + (size_t)r * (3 * DIMC) + c);
        sQ[r * LDQK + c + 0] = f2tff(v.x * SCALE);
        sQ[r * LDQK + c + 1] = f2tff(v.y * SCALE);
        sQ[r * LDQK + c + 2] = f2tff(v.z * SCALE);
        sQ[r * LDQK + c + 3] = f2tff(v.w * SCALE);
    }
    __syncthreads();
    if (tid < BR) {
        float s = 0.f;
        #pragma unroll 8
        for (int c = 0; c < DIMC; c++) { float x = sQ[tid * LDQK + c]; s += x * x; }
        sQ2[tid] = s;
    }
    __syncthreads();

    const int r0 = warp * 16 + g;          // this thread's first row within tile
    const float q2a = sQ2[r0];
    const float q2b = sQ2[r0 + 8];

    float m0 = -3e38f, m1 = -3e38f, l0 = 0.f, l1 = 0.f;
    float o[24][4];
    #pragma unroll
    for (int n = 0; n < 24; n++) { o[n][0] = 0.f; o[n][1] = 0.f; o[n][2] = 0.f; o[n][3] = 0.f; }

    float* sPw = sP + warp * 16 * LDP;

    for (int st = 0; st < NTOK / BC; ++st) {
        __syncthreads();   // previous-iteration consumers of sK/sV/sP done

        // ---- load K (scaled, tf32) and V (tf32) tiles ----
        const float* kptr = qkv + ((size_t)b * NTOK + st * BC) * (3 * DIMC) + DIMC;
        const float* vptr = kptr + DIMC;
        for (int idx = tid * 4; idx < BC * DIMC; idx += NTHREADS * 4) {
            int r = idx / DIMC, c = idx % DIMC;
            float4 kv = *(const float4*)(kptr + (size_t)r * (3 * DIMC) + c);
            sK[r * LDQK + c + 0] = f2tff(kv.x * SCALE);
            sK[r * LDQK + c + 1] = f2tff(kv.y * SCALE);
            sK[r * LDQK + c + 2] = f2tff(kv.z * SCALE);
            sK[r * LDQK + c + 3] = f2tff(kv.w * SCALE);
            float4 vv = *(const float4*)(vptr + (size_t)r * (3 * DIMC) + c);
            sV[r * LDV + c + 0] = f2tff(vv.x);
            sV[r * LDV + c + 1] = f2tff(vv.y);
            sV[r * LDV + c + 2] = f2tff(vv.z);
            sV[r * LDV + c + 3] = f2tff(vv.w);
        }
        __syncthreads();
        if (tid < BC) {
            float s = 0.f;
            #pragma unroll 8
            for (int c = 0; c < DIMC; c++) { float x = sK[tid * LDQK + c]; s += x * x; }
            sK2[tid] = s;
        }
        __syncthreads();

        // ---- S = Q K^T  (per warp: 16 x 64) ----
        float sacc[8][4];
        #pragma unroll
        for (int n = 0; n < 8; n++) { sacc[n][0]=0.f; sacc[n][1]=0.f; sacc[n][2]=0.f; sacc[n][3]=0.f; }

        for (int kk = 0; kk < DIMC; kk += 8) {
            uint32_t a0 = __float_as_uint(sQ[(r0)     * LDQK + kk     + t4]);
            uint32_t a1 = __float_as_uint(sQ[(r0 + 8) * LDQK + kk     + t4]);
            uint32_t a2 = __float_as_uint(sQ[(r0)     * LDQK + kk + 4 + t4]);
            uint32_t a3 = __float_as_uint(sQ[(r0 + 8) * LDQK + kk + 4 + t4]);
            #pragma unroll
            for (int n = 0; n < 8; n++) {
                uint32_t b0 = __float_as_uint(sK[(n * 8 + g) * LDQK + kk     + t4]);
                uint32_t b1 = __float_as_uint(sK[(n * 8 + g) * LDQK + kk + 4 + t4]);
                mma8(sacc[n], a0, a1, a2, a3, b0, b1);
            }
        }

        // ---- logits + online softmax ----
        float rmax0 = -3e38f, rmax1 = -3e38f;
        #pragma unroll
        for (int n = 0; n < 8; n++) {
            int col = n * 8 + 2 * t4;
            float k2c0 = sK2[col], k2c1 = sK2[col + 1];
            float d;
            d = fmaxf(q2a + k2c0 - 2.f * sacc[n][0], 0.f); sacc[n][0] = -sqrtf(d);
            d = fmaxf(q2a + k2c1 - 2.f * sacc[n][1], 0.f); sacc[n][1] = -sqrtf(d);
            d = fmaxf(q2b + k2c0 - 2.f * sacc[n][2], 0.f); sacc[n][2] = -sqrtf(d);
            d = fmaxf(q2b + k2c1 - 2.f * sacc[n][3], 0.f); sacc[n][3] = -sqrtf(d);
            rmax0 = fmaxf(rmax0, fmaxf(sacc[n][0], sacc[n][1]));
            rmax1 = fmaxf(rmax1, fmaxf(sacc[n][2], sacc[n][3]));
        }
        rmax0 = fmaxf(rmax0, __shfl_xor_sync(0xffffffffu, rmax0, 1));
        rmax0 = fmaxf(rmax0, __shfl_xor_sync(0xffffffffu, rmax0, 2));
        rmax1 = fmaxf(rmax1, __shfl_xor_sync(0xffffffffu, rmax1, 1));
        rmax1 = fmaxf(rmax1, __shfl_xor_sync(0xffffffffu, rmax1, 2));
        float mn0 = fmaxf(m0, rmax0), mn1 = fmaxf(m1, rmax1);
        float c0 = __expf(m0 - mn0),  c1 = __expf(m1 - mn1);
        m0 = mn0; m1 = mn1;

        float rs0 = 0.f, rs1 = 0.f;
        #pragma unroll
        for (int n = 0; n < 8; n++) {
            float p0 = __expf(sacc[n][0] - m0);
            float p1 = __expf(sacc[n][1] - m0);
            float p2 = __expf(sacc[n][2] - m1);
            float p3 = __expf(sacc[n][3] - m1);
            rs0 += p0 + p1; rs1 += p2 + p3;
            int col = n * 8 + 2 * t4;
            sPw[(g)     * LDP + col    ] = f2tff(p0);
            sPw[(g)     * LDP + col + 1] = f2tff(p1);
            sPw[(g + 8) * LDP + col    ] = f2tff(p2);
            sPw[(g + 8) * LDP + col + 1] = f2tff(p3);
        }
        rs0 += __shfl_xor_sync(0xffffffffu, rs0, 1);
        rs0 += __shfl_xor_sync(0xffffffffu, rs0, 2);
        rs1 += __shfl_xor_sync(0xffffffffu, rs1, 1);
        rs1 += __shfl_xor_sync(0xffffffffu, rs1, 2);
        l0 = l0 * c0 + rs0;
        l1 = l1 * c1 + rs1;

        #pragma unroll
        for (int n = 0; n < 24; n++) {
            o[n][0] *= c0; o[n][1] *= c0; o[n][2] *= c1; o[n][3] *= c1;
        }

        __syncwarp();   // P staging visible to whole warp

        // ---- O += P V  (per warp: 16 x 192) ----
        for (int kk = 0; kk < BC; kk += 8) {
            uint32_t a0 = __float_as_uint(sPw[(g)     * LDP + kk     + t4]);
            uint32_t a1 = __float_as_uint(sPw[(g + 8) * LDP + kk     + t4]);
            uint32_t a2 = __float_as_uint(sPw[(g)     * LDP + kk + 4 + t4]);
            uint32_t a3 = __float_as_uint(sPw[(g + 8) * LDP + kk + 4 + t4]);
            #pragma unroll
            for (int n = 0; n < 24; n++) {
                uint32_t b0 = __float_as_uint(sV[(kk +     t4) * LDV + n * 8 + g]);
                uint32_t b1 = __float_as_uint(sV[(kk + 4 + t4) * LDV + n * 8 + g]);
                mma8(o[n], a0, a1, a2, a3, b0, b1);
            }
        }
        // next-iteration __syncthreads() orders P reads vs. the next P writes
    }

    // ---- epilogue ----
    float il0 = 1.f / l0, il1 = 1.f / l1;
    size_t orow0 = ((size_t)b * NTOK + q0 + r0) * DIMC;
    size_t orow1 = orow0 + (size_t)8 * DIMC;
    #pragma unroll
    for (int n = 0; n < 24; n++) {
        int col = n * 8 + 2 * t4;
        float2 u0 = make_float2(o[n][0] * il0, o[n][1] * il0);
        float2 u1 = make_float2(o[n][2] * il1, o[n][3] * il1);
        *(float2*)(out + orow0 + col) = u0;
        *(float2*)(out + orow1 + col) = u1;
    }
}

extern "C" void kernel_launch(void* const* d_in, const int* in_sizes, int n_in,
                              void* d_out, int out_size) {
    const float* qkv = (const float*)d_in[0];
    float* out = (float*)d_out;
    cudaFuncSetAttribute(qkv_l2attn_kernel,
                         cudaFuncAttributeMaxDynamicSharedMemorySize, SMEM_BYTES);
    dim3 grid(NTOK / BR, NB);
    qkv_l2attn_kernel<<<grid, NTHREADS, SMEM_BYTES>>>(qkv, out);
}

// round 2
// speedup vs baseline: 2.2137x; 2.2137x over previous
#include <cuda_runtime.h>
#include <cstdint>
#include <cstddef>

#define DIMC 192
#define NB   8
#define NTOK 4096
#define BR   128
#define BC   64
#define LDQK 196   // 196 % 32 == 4  -> conflict-free Q/K fragment loads (bank = 4g + t4)
#define LDV  200   // 200 % 32 == 8  -> conflict-free V fragment loads  (bank = 8t4 + g)
#define NTHREADS 256
#define NWARPS   (NTHREADS/32)
#define SCALE 0.07216878364870322f   /* 192^-0.5 */

// smem layout (floats)
#define SQ_SZ  (BR*LDQK)
#define SK_SZ  (BC*LDQK)
#define SV_SZ  (BC*LDV)
#define SMEM_FLOATS (SQ_SZ + SK_SZ + SV_SZ + BR + BC)
#define SMEM_BYTES  (SMEM_FLOATS * 4)

__device__ __forceinline__ float f2tff(float f) {
    uint32_t u;
    asm("cvt.rna.tf32.f32 %0, %1;" : "=r"(u) : "f"(f));
    return __uint_as_float(u);
}

__device__ __forceinline__ float sqrt_approx(float x) {
    float r;
    asm("sqrt.approx.f32 %0, %1;" : "=f"(r) : "f"(x));
    return r;
}

__device__ __forceinline__ void mma8(float* c,
        uint32_t a0, uint32_t a1, uint32_t a2, uint32_t a3,
        uint32_t b0, uint32_t b1) {
    asm volatile("mma.sync.aligned.m16n8k8.row.col.f32.tf32.tf32.f32 "
        "{%0,%1,%2,%3}, {%4,%5,%6,%7}, {%8,%9}, {%0,%1,%2,%3};"
        : "+f"(c[0]), "+f"(c[1]), "+f"(c[2]), "+f"(c[3])
        : "r"(a0), "r"(a1), "r"(a2), "r"(a3), "r"(b0), "r"(b1));
}

__global__ void __launch_bounds__(NTHREADS, 1)
qkv_l2attn_kernel(const float* __restrict__ qkv, float* __restrict__ out)
{
    extern __shared__ float sm[];
    float* sQ  = sm;
    float* sK  = sQ + SQ_SZ;
    float* sV  = sK + SK_SZ;
    float* sQ2 = sV + SV_SZ;
    float* sK2 = sQ2 + BR;

    const int tid  = threadIdx.x;
    const int warp = tid >> 5;
    const int lane = tid & 31;
    const int g    = lane >> 2;   // group (row within 8-row band)
    const int t4   = lane & 3;    // thread-in-group

    const int b  = blockIdx.y;
    const int q0 = blockIdx.x * BR;

    // ---- load Q tile (scaled, tf32-rounded) ----
    const float* qptr = qkv + ((size_t)b * NTOK + q0) * (3 * DIMC);
    for (int idx = tid * 4; idx < BR * DIMC; idx += NTHREADS * 4) {
        int r = idx / DIMC, c = idx % DIMC;
        float4 v = *(const float4*)(qptr + (size_t)r * (3 * DIMC) + c);
        sQ[r * LDQK + c + 0] = f2tff(v.x * SCALE);
        sQ[r * LDQK + c + 1] = f2tff(v.y * SCALE);
        sQ[r * LDQK + c + 2] = f2tff(v.z * SCALE);
        sQ[r * LDQK + c + 3] = f2tff(v.w * SCALE);
    }
    __syncthreads();
    if (tid < BR) {
        float s = 0.f;
        #pragma unroll 8
        for (int c = 0; c < DIMC; c++) { float x = sQ[tid * LDQK + c]; s += x * x; }
        sQ2[tid] = s;
    }
    __syncthreads();

    const int r0 = warp * 16 + g;          // this thread's first row within tile
    const float q2a = sQ2[r0];
    const float q2b = sQ2[r0 + 8];

    float m0 = -3e38f, m1 = -3e38f, l0 = 0.f, l1 = 0.f;
    float o[24][4];
    #pragma unroll
    for (int n = 0; n < 24; n++) { o[n][0] = 0.f; o[n][1] = 0.f; o[n][2] = 0.f; o[n][3] = 0.f; }

    const int src_lo = (lane & ~3) | (t4 >> 1);   // lane holding P col (t4 rounded down to pair)
    const int src_hi = src_lo + 2;                // lane holding P col t4+4's pair
    const bool oddc  = (t4 & 1);

    for (int st = 0; st < NTOK / BC; ++st) {
        __syncthreads();   // previous-iteration consumers of sK/sV done

        // ---- load K (scaled, tf32) and V (tf32) tiles ----
        const float* kptr = qkv + ((size_t)b * NTOK + st * BC) * (3 * DIMC) + DIMC;
        const float* vptr = kptr + DIMC;
        for (int idx = tid * 4; idx < BC * DIMC; idx += NTHREADS * 4) {
            int r = idx / DIMC, c = idx % DIMC;
            float4 kv = *(const float4*)(kptr + (size_t)r * (3 * DIMC) + c);
            sK[r * LDQK + c + 0] = f2tff(kv.x * SCALE);
            sK[r * LDQK + c + 1] = f2tff(kv.y * SCALE);
            sK[r * LDQK + c + 2] = f2tff(kv.z * SCALE);
            sK[r * LDQK + c + 3] = f2tff(kv.w * SCALE);
            float4 vv = *(const float4*)(vptr + (size_t)r * (3 * DIMC) + c);
            sV[r * LDV + c + 0] = f2tff(vv.x);
            sV[r * LDV + c + 1] = f2tff(vv.y);
            sV[r * LDV + c + 2] = f2tff(vv.z);
            sV[r * LDV + c + 3] = f2tff(vv.w);
        }
        __syncthreads();
        if (tid < BC) {
            float s = 0.f;
            #pragma unroll 8
            for (int c = 0; c < DIMC; c++) { float x = sK[tid * LDQK + c]; s += x * x; }
            sK2[tid] = s;
        }
        __syncthreads();

        // ---- S = Q K^T  (per warp: 16 x 64) ----
        float sacc[8][4];
        #pragma unroll
        for (int n = 0; n < 8; n++) { sacc[n][0]=0.f; sacc[n][1]=0.f; sacc[n][2]=0.f; sacc[n][3]=0.f; }

        for (int kk = 0; kk < DIMC; kk += 8) {
            uint32_t a0 = __float_as_uint(sQ[(r0)     * LDQK + kk     + t4]);
            uint32_t a1 = __float_as_uint(sQ[(r0 + 8) * LDQK + kk     + t4]);
            uint32_t a2 = __float_as_uint(sQ[(r0)     * LDQK + kk + 4 + t4]);
            uint32_t a3 = __float_as_uint(sQ[(r0 + 8) * LDQK + kk + 4 + t4]);
            #pragma unroll
            for (int n = 0; n < 8; n++) {
                uint32_t b0 = __float_as_uint(sK[(n * 8 + g) * LDQK + kk     + t4]);
                uint32_t b1 = __float_as_uint(sK[(n * 8 + g) * LDQK + kk + 4 + t4]);
                mma8(sacc[n], a0, a1, a2, a3, b0, b1);
            }
        }

        // ---- logits: -dist, then row max ----
        float rmax0 = -3e38f, rmax1 = -3e38f;
        #pragma unroll
        for (int n = 0; n < 8; n++) {
            float2 k2 = *(const float2*)(sK2 + n * 8 + 2 * t4);
            float d;
            d = fmaxf(q2a + k2.x - 2.f * sacc[n][0], 0.f); sacc[n][0] = -sqrt_approx(d);
            d = fmaxf(q2a + k2.y - 2.f * sacc[n][1], 0.f); sacc[n][1] = -sqrt_approx(d);
            d = fmaxf(q2b + k2.x - 2.f * sacc[n][2], 0.f); sacc[n][2] = -sqrt_approx(d);
            d = fmaxf(q2b + k2.y - 2.f * sacc[n][3], 0.f); sacc[n][3] = -sqrt_approx(d);
            rmax0 = fmaxf(rmax0, fmaxf(sacc[n][0], sacc[n][1]));
            rmax1 = fmaxf(rmax1, fmaxf(sacc[n][2], sacc[n][3]));
        }
        rmax0 = fmaxf(rmax0, __shfl_xor_sync(0xffffffffu, rmax0, 1));
        rmax0 = fmaxf(rmax0, __shfl_xor_sync(0xffffffffu, rmax0, 2));
        rmax1 = fmaxf(rmax1, __shfl_xor_sync(0xffffffffu, rmax1, 1));
        rmax1 = fmaxf(rmax1, __shfl_xor_sync(0xffffffffu, rmax1, 2));
        float mn0 = fmaxf(m0, rmax0), mn1 = fmaxf(m1, rmax1);
        float c0 = __expf(m0 - mn0),  c1 = __expf(m1 - mn1);
        m0 = mn0; m1 = mn1;

        // rescale O before accumulating this tile
        #pragma unroll
        for (int n = 0; n < 24; n++) {
            o[n][0] *= c0; o[n][1] *= c0; o[n][2] *= c1; o[n][3] *= c1;
        }

        // ---- exp + shuffle re-fragmentation + PV MMA, one 8-key chunk at a time ----
        float rs0 = 0.f, rs1 = 0.f;
        #pragma unroll
        for (int n = 0; n < 8; n++) {
            float p0 = __expf(sacc[n][0] - m0);   // (g,    2t4)
            float p1 = __expf(sacc[n][1] - m0);   // (g,    2t4+1)
            float p2 = __expf(sacc[n][2] - m1);   // (g+8,  2t4)
            float p3 = __expf(sacc[n][3] - m1);   // (g+8,  2t4+1)
            rs0 += p0 + p1; rs1 += p2 + p3;

            // C-layout -> A-layout: A needs cols t4 (a0/a1) and t4+4 (a2/a3)
            float v0 = __shfl_sync(0xffffffffu, p0, src_lo);
            float v1 = __shfl_sync(0xffffffffu, p1, src_lo);
            float w0 = __shfl_sync(0xffffffffu, p0, src_hi);
            float w1 = __shfl_sync(0xffffffffu, p1, src_hi);
            float x0 = __shfl_sync(0xffffffffu, p2, src_lo);
            float x1 = __shfl_sync(0xffffffffu, p3, src_lo);
            float y0 = __shfl_sync(0xffffffffu, p2, src_hi);
            float y1 = __shfl_sync(0xffffffffu, p3, src_hi);
            uint32_t a0 = __float_as_uint(f2tff(oddc ? v1 : v0));
            uint32_t a1 = __float_as_uint(f2tff(oddc ? x1 : x0));
            uint32_t a2 = __float_as_uint(f2tff(oddc ? w1 : w0));
            uint32_t a3 = __float_as_uint(f2tff(oddc ? y1 : y0));

            const int kk = n * 8;
            #pragma unroll
            for (int nn = 0; nn < 24; nn++) {
                uint32_t b0 = __float_as_uint(sV[(kk +     t4) * LDV + nn * 8 + g]);
                uint32_t b1 = __float_as_uint(sV[(kk + 4 + t4) * LDV + nn * 8 + g]);
                mma8(o[nn], a0, a1, a2, a3, b0, b1);
            }
        }
        rs0 += __shfl_xor_sync(0xffffffffu, rs0, 1);
        rs0 += __shfl_xor_sync(0xffffffffu, rs0, 2);
        rs1 += __shfl_xor_sync(0xffffffffu, rs1, 1);
        rs1 += __shfl_xor_sync(0xffffffffu, rs1, 2);
        l0 = l0 * c0 + rs0;
        l1 = l1 * c1 + rs1;
    }

    // ---- epilogue ----
    float il0 = 1.f / l0, il1 = 1.f / l1;
    size_t orow0 = ((size_t)b * NTOK + q0 + r0) * DIMC;
    size_t orow1 = orow0 + (size_t)8 * DIMC;
    #pragma unroll
    for (int n = 0; n < 24; n++) {
        int col = n * 8 + 2 * t4;
        float2 u0 = make_float2(o[n][0] * il0, o[n][1] * il0);
        float2 u1 = make_float2(o[n][2] * il1, o[n][3] * il1);
        *(float2*)(out + orow0 + col) = u0;
        *(float2*)(out + orow1 + col) = u1;
    }
}

extern "C" void kernel_launch(void* const* d_in, const int* in_sizes, int n_in,
                              void* d_out, int out_size) {
    const float* qkv = (const float*)d_in[0];
    float* out = (float*)d_out;
    cudaFuncSetAttribute(qkv_l2attn_kernel,
                         cudaFuncAttributeMaxDynamicSharedMemorySize, SMEM_BYTES);
    dim3 grid(NTOK / BR, NB);
    qkv_l2attn_kernel<<<grid, NTHREADS, SMEM_BYTES>>>(qkv, out);
}